// round 2
// baseline (speedup 1.0000x reference)
#include <cuda_runtime.h>
#include <math.h>

// Problem constants (fixed by the reference setup_inputs).
#define NTEST  8192
#define NTRAIN 8192
#define DIM    256

#define BM 128
#define BN 128
#define BK 32
#define SPLIT 4   // split over the train dimension -> 64*4 = 256 CTAs

// Scratch for precomputed squared norms (allocation-free rule: __device__ globals).
__device__ float g_XX[NTEST];
__device__ float g_YY[NTRAIN];

// ---------------------------------------------------------------------------
// Kernel 1: squared row norms of Xtest / Xtrain, and out[n] = mean_const init.
// One warp per row, coalesced loads, shfl reduction.
// ---------------------------------------------------------------------------
__global__ void gp_precompute_kernel(const float* __restrict__ Xtest,
                                     const float* __restrict__ Xtrain,
                                     const float* __restrict__ mean_const,
                                     float* __restrict__ out)
{
    const int warp = threadIdx.x >> 5;
    const int lane = threadIdx.x & 31;
    int row = blockIdx.x * 8 + warp;            // 8 warps per block
    if (row >= NTEST + NTRAIN) return;

    const float* X;
    float* dst;
    bool isTest;
    if (row < NTEST) { X = Xtest;  dst = g_XX; isTest = true; }
    else             { row -= NTEST; X = Xtrain; dst = g_YY; isTest = false; }

    const float* p = X + (size_t)row * DIM;
    float s = 0.f;
    #pragma unroll
    for (int d = 0; d < DIM / 32; d++) {
        float v = p[lane + d * 32];
        s = fmaf(v, v, s);
    }
    #pragma unroll
    for (int o = 16; o > 0; o >>= 1) s += __shfl_xor_sync(0xffffffffu, s, o);

    if (lane == 0) {
        dst[row] = s;
        if (isTest) out[row] = *mean_const;     // constant-mean init
    }
}

// ---------------------------------------------------------------------------
// Kernel 2: fused RBF-cov GEMM + exp + matvec with mu.
//
// Each CTA: 128 test rows x (NTRAIN/SPLIT) train rows, in 128-wide chunks.
// Inner: 128x128x32 register-blocked fp32 GEMM (8x8 per thread) with
// XOR-swizzled k-major smem tiles (conflict-free transpose STS + LDS.128).
// Epilogue per chunk: sqdist -> underflow-exact exp cutoff -> dot with mu.
// ---------------------------------------------------------------------------
__global__ __launch_bounds__(256)
void gp_main_kernel(const float* __restrict__ Xtest,
                    const float* __restrict__ Xtrain,
                    const float* __restrict__ mu,
                    const float* __restrict__ ls_p,
                    const float* __restrict__ sv_p,
                    float* __restrict__ out)
{
    __shared__ float As[BK * BM];   // A[row][k] stored at As[k*128 + (row ^ (k&28))]
    __shared__ float Bs[BK * BM];
    __shared__ float sYY[BN];
    __shared__ float sMu[BN];

    const int tid = threadIdx.x;
    const int ty  = tid >> 4;       // 0..15 : row group (8 rows)
    const int tx  = tid & 15;       // 0..15 : col group (8 cols)
    const int lr  = tid >> 3;       // 0..31 : load row within 32-row pass
    const int lc  = tid & 7;        // 0..7  : load col group (float4)

    const int rb   = blockIdx.x & 63;
    const int sp   = blockIdx.x >> 6;
    const int row0 = rb * BM;
    const int mbeg = sp * (NTRAIN / SPLIT);

    const float l      = *ls_p;
    const float negInv = -0.5f / (l * l);
    // exp(s * negInv) == 0.0f exactly (fp32, incl. denormals) once s >= 211*l^2.
    const float sCut   = 211.0f * l * l;

    float xx[8];
    #pragma unroll
    for (int i = 0; i < 8; i++) xx[i] = g_XX[row0 + ty * 8 + i];

    float acc[8];
    #pragma unroll
    for (int i = 0; i < 8; i++) acc[i] = 0.f;

    const float* Aptr = Xtest + (size_t)(row0 + lr) * DIM + lc * 4;

    for (int mc = 0; mc < NTRAIN / SPLIT; mc += BN) {
        const int m0 = mbeg + mc;

        __syncthreads();   // previous chunk's epilogue smem reads complete
        if (tid < BN) sYY[tid] = g_YY[m0 + tid];
        else          sMu[tid - BN] = mu[m0 + tid - BN];

        const float* Bptr = Xtrain + (size_t)(m0 + lr) * DIM + lc * 4;

        float cross[64];
        #pragma unroll
        for (int i = 0; i < 64; i++) cross[i] = 0.f;

        // Prefetch k-tile 0 into registers.
        float4 ra[4], rb4[4];
        #pragma unroll
        for (int p = 0; p < 4; p++) {
            ra[p]  = *(const float4*)(Aptr + (size_t)p * 32 * DIM);
            rb4[p] = *(const float4*)(Bptr + (size_t)p * 32 * DIM);
        }

        #pragma unroll 1
        for (int kt = 0; kt < DIM / BK; kt++) {
            __syncthreads();   // smem tiles free
            // Transpose-store staged registers (conflict-free via XOR swizzle).
            #pragma unroll
            for (int p = 0; p < 4; p++) {
                const int r = p * 32 + lr;
                float va[4] = {ra[p].x,  ra[p].y,  ra[p].z,  ra[p].w};
                float vb[4] = {rb4[p].x, rb4[p].y, rb4[p].z, rb4[p].w};
                #pragma unroll
                for (int j = 0; j < 4; j++) {
                    const int k = lc * 4 + j;
                    const int sw = r ^ (k & 28);
                    As[k * BM + sw] = va[j];
                    Bs[k * BM + sw] = vb[j];
                }
            }
            __syncthreads();

            // Prefetch next k-tile while computing from smem.
            if (kt + 1 < DIM / BK) {
                const int koff = (kt + 1) * BK;
                #pragma unroll
                for (int p = 0; p < 4; p++) {
                    ra[p]  = *(const float4*)(Aptr + (size_t)p * 32 * DIM + koff);
                    rb4[p] = *(const float4*)(Bptr + (size_t)p * 32 * DIM + koff);
                }
            }

            #pragma unroll
            for (int k = 0; k < BK; k++) {
                const int sw = k & 28;
                const float4 a0 = *(const float4*)&As[k * BM + ((ty * 8) ^ sw)];
                const float4 a1 = *(const float4*)&As[k * BM + (((ty * 8) ^ sw) ^ 4)];
                const float4 b0 = *(const float4*)&Bs[k * BM + ((tx * 8) ^ sw)];
                const float4 b1 = *(const float4*)&Bs[k * BM + (((tx * 8) ^ sw) ^ 4)];
                const float a[8] = {a0.x, a0.y, a0.z, a0.w, a1.x, a1.y, a1.z, a1.w};
                const float b[8] = {b0.x, b0.y, b0.z, b0.w, b1.x, b1.y, b1.z, b1.w};
                #pragma unroll
                for (int i = 0; i < 8; i++)
                    #pragma unroll
                    for (int j = 0; j < 8; j++)
                        cross[i * 8 + j] = fmaf(a[i], b[j], cross[i * 8 + j]);
            }
        }

        // ---- epilogue: sqdist -> exp (underflow-exact skip) -> dot with mu ----
        float yyf[8], muf[8];
        #pragma unroll
        for (int j = 0; j < 8; j++) {
            yyf[j] = sYY[tx * 8 + j];
            muf[j] = sMu[tx * 8 + j];
        }

        float smin = 3.4e38f;
        #pragma unroll
        for (int i = 0; i < 8; i++)
            #pragma unroll
            for (int j = 0; j < 8; j++) {
                float s = fmaf(-2.f, cross[i * 8 + j], xx[i] + yyf[j]);
                s = fmaxf(s, 0.f);
                smin = fminf(smin, s);
            }

        if (smin < sCut) {   // rare: at least one pair whose exp doesn't underflow
            #pragma unroll
            for (int i = 0; i < 8; i++)
                #pragma unroll
                for (int j = 0; j < 8; j++) {
                    float s = fmaxf(fmaf(-2.f, cross[i * 8 + j], xx[i] + yyf[j]), 0.f);
                    acc[i] = fmaf(expf(s * negInv), muf[j], acc[i]);
                }
        }
    }

    // Reduce partial row sums across the 16 tx lanes (stays within the warp).
    const float sv = *sv_p;
    #pragma unroll
    for (int i = 0; i < 8; i++) {
        float v = acc[i];
        #pragma unroll
        for (int o = 1; o < 16; o <<= 1) v += __shfl_xor_sync(0xffffffffu, v, o);
        if (tx == 0) atomicAdd(&out[row0 + ty * 8 + i], sv * v);
    }
}

// ---------------------------------------------------------------------------
// kernel_launch: inputs in metadata order:
//   0 Xtest [8192,256] f32, 1 Xtrain [8192,256] f32, 2 mu [8192] f32,
//   3 mean_const [] f32, 4 lengthscale [] f32, 5 signal_var [] f32
// ---------------------------------------------------------------------------
extern "C" void kernel_launch(void* const* d_in, const int* in_sizes, int n_in,
                              void* d_out, int out_size)
{
    const float* Xtest      = (const float*)d_in[0];
    const float* Xtrain     = (const float*)d_in[1];
    const float* mu         = (const float*)d_in[2];
    const float* mean_const = (const float*)d_in[3];
    const float* lengthsc   = (const float*)d_in[4];
    const float* signal_var = (const float*)d_in[5];
    float* out = (float*)d_out;

    // Row norms + output init (mean term). 8 rows per 256-thread block.
    gp_precompute_kernel<<<(NTEST + NTRAIN) / 8, 256>>>(Xtest, Xtrain, mean_const, out);

    // Fused cov*mu.
    gp_main_kernel<<<(NTEST / BM) * SPLIT, 256>>>(Xtest, Xtrain, mu, lengthsc, signal_var, out);
}

// round 4
// speedup vs baseline: 3.4845x; 3.4845x over previous
#include <cuda_runtime.h>
#include <cuda_bf16.h>
#include <math.h>
#include <stdint.h>

// ============================================================================
// Problem constants (fixed by reference setup_inputs)
// ============================================================================
#define NTEST  8192
#define NTRAIN 8192
#define DIM    256

#define TM 128
#define TN 128
#define N_ROW_TILES (NTEST / TM)               // 64
#define N_COL_TILES (NTRAIN / TN)              // 64
#define TOT_TILES   (N_ROW_TILES * N_COL_TILES) // 4096
#define GRID 296                                // 2 balanced waves on 148 SMs

// Scratch (__device__ globals: allocation-free rule)
__device__ float g_XX[NTEST];
__device__ float g_YY[NTRAIN];
__device__ __align__(128) __nv_bfloat16 g_At[NTEST  * DIM];
__device__ __align__(128) __nv_bfloat16 g_Bt[NTRAIN * DIM];

// ============================================================================
// helpers
// ============================================================================
__device__ __forceinline__ uint32_t smem_u32(const void* p) {
    uint32_t a;
    asm("{ .reg .u64 t; cvta.to.shared.u64 t, %1; cvt.u32.u64 %0, t; }" : "=r"(a) : "l"(p));
    return a;
}
__device__ __forceinline__ void cp16(uint32_t dst, const void* src) {
    asm volatile("cp.async.cg.shared.global [%0], [%1], 16;" :: "r"(dst), "l"(src));
}
#define CP_COMMIT() asm volatile("cp.async.commit_group;" ::: "memory")

__device__ __forceinline__ void ldsm_x4(uint32_t (&r)[4], uint32_t addr) {
    asm volatile("ldmatrix.sync.aligned.m8n8.x4.shared.b16 {%0,%1,%2,%3}, [%4];"
                 : "=r"(r[0]), "=r"(r[1]), "=r"(r[2]), "=r"(r[3]) : "r"(addr));
}
__device__ __forceinline__ void mma_16816(float (&c)[4], const uint32_t (&a)[4],
                                          uint32_t b0, uint32_t b1) {
    asm volatile(
        "mma.sync.aligned.m16n8k16.row.col.f32.bf16.bf16.f32 "
        "{%0,%1,%2,%3}, {%4,%5,%6,%7}, {%8,%9}, {%0,%1,%2,%3};"
        : "+f"(c[0]), "+f"(c[1]), "+f"(c[2]), "+f"(c[3])
        : "r"(a[0]), "r"(a[1]), "r"(a[2]), "r"(a[3]), "r"(b0), "r"(b1));
}

// ============================================================================
// Kernel 1: norms + bf16 conversion + out[] = mean_const init
// ============================================================================
__global__ void gp_precompute_kernel(const float* __restrict__ Xtest,
                                     const float* __restrict__ Xtrain,
                                     const float* __restrict__ mean_const,
                                     float* __restrict__ out)
{
    const int warp = threadIdx.x >> 5;
    const int lane = threadIdx.x & 31;
    int row = blockIdx.x * 8 + warp;
    if (row >= NTEST + NTRAIN) return;

    const float* X; float* dst; __nv_bfloat16* bdst; bool isTest;
    if (row < NTEST) { X = Xtest;  dst = g_XX; bdst = g_At; isTest = true; }
    else { row -= NTEST; X = Xtrain; dst = g_YY; bdst = g_Bt; isTest = false; }

    const float* p = X + (size_t)row * DIM;
    __nv_bfloat16* bp = bdst + (size_t)row * DIM;
    float s = 0.f;
    #pragma unroll
    for (int d = 0; d < DIM / 32; d++) {
        float v = p[lane + d * 32];
        s = fmaf(v, v, s);
        bp[lane + d * 32] = __float2bfloat16_rn(v);
    }
    #pragma unroll
    for (int o = 16; o > 0; o >>= 1) s += __shfl_xor_sync(0xffffffffu, s, o);
    if (lane == 0) {
        dst[row] = s;
        if (isTest) out[row] = *mean_const;
    }
}

// ============================================================================
// Kernel 2: HMMA screening GEMM + underflow-exact epilogue.
//
// smem tile layout (A and B identical): 128 rows x 256 bf16, stored as 4
// sub-tiles of 128x64 (kc = k/64); within a sub-tile row stride is 128 B and
// byte-chunk c (16 B units) is XOR-swizzled by (row&7)<<4 -> conflict-free
// cp.async stores and ldmatrix loads.
// ============================================================================
__global__ __launch_bounds__(256, 1)
void gp_hmma_kernel(const float* __restrict__ Xtest,
                    const float* __restrict__ Xtrain,
                    const float* __restrict__ mu,
                    const float* __restrict__ ls_p,
                    const float* __restrict__ sv_p,
                    float* __restrict__ out)
{
    extern __shared__ char dsm[];
    __shared__ float s_yy[2][TN];
    __shared__ float s_mu[2][TN];

    const int tid  = threadIdx.x;
    const int wid  = tid >> 5;
    const int lane = tid & 31;
    const int bid  = blockIdx.x;

    const uint32_t dsm_u = smem_u32(dsm);
    const uint32_t uA  = (dsm_u + 1023u) & ~1023u;
    const uint32_t uB0 = uA  + 65536u;
    const uint32_t uB1 = uB0 + 65536u;

    const int warp_m = (wid & 3) * 32;   // 4 warps along M
    const int warp_n = (wid >> 2) * 64;  // 2 warps along N

    // ldmatrix lane geometry
    const int rA0   = warp_m + (lane & 15);
    const uint32_t swA = (uint32_t)((rA0 & 7) << 4);
    const uint32_t aKl = (uint32_t)((lane >> 4) << 4);
    const int rB0   = warp_n + (lane & 7) + ((lane >> 4) << 3);
    const uint32_t swB = (uint32_t)((rB0 & 7) << 4);
    const uint32_t bKl = (uint32_t)(((lane >> 3) & 1) << 4);

    const float l      = *ls_p;
    const float negInv = -0.5f / (l * l);
    const float sCut   = 211.0f * l * l;   // expf == exactly 0 above this
    const float sv     = *sv_p;

    const int t_begin = (int)(((long long)bid     * TOT_TILES) / GRID);
    const int t_end   = (int)(((long long)(bid+1) * TOT_TILES) / GRID);

    // tile fill: 4096 x 16B chunks via cp.async with swizzle
    auto fill_tile = [&](uint32_t ubase, const __nv_bfloat16* src) {
        #pragma unroll
        for (int q0 = 0; q0 < 16; q0++) {
            const int q = q0 * 256 + tid;
            const int r = q >> 5, c16 = q & 31;
            const uint32_t dst = ubase + (uint32_t)(((c16 >> 3) << 14) + (r << 7)
                                + (((c16 & 7) << 4) ^ ((r & 7) << 4)));
            cp16(dst, src + r * DIM + c16 * 8);
        }
    };

    int i = t_begin;
    while (i < t_end) {
        const int rt      = i >> 6;
        const int seg_end = min(t_end, (rt + 1) << 6);
        const int n       = seg_end - i;
        const int row0    = rt * TM;

        // A block for this row segment
        fill_tile(uA, g_At + (size_t)row0 * DIM);
        CP_COMMIT();
        // first B tile
        {
            const int n0 = (i & 63) * TN;
            fill_tile(uB0, g_Bt + (size_t)n0 * DIM);
            CP_COMMIT();
            if (tid < TN) s_yy[0][tid] = g_YY[n0 + tid];
            else          s_mu[0][tid - TN] = mu[n0 + tid - TN];
        }

        // per-thread xx values (4 rows)
        float xv[4];
        #pragma unroll
        for (int j = 0; j < 4; j++) xv[j] = g_XX[row0 + warp_m + (lane >> 2) + 8 * j];

        for (int tl = 0; tl < n; tl++) {
            const int buf = tl & 1;
            const uint32_t uB = buf ? uB1 : uB0;

            const bool more = (tl + 1 < n);
            if (more) {
                const int n0n = ((i + tl + 1) & 63) * TN;
                fill_tile(buf ? uB0 : uB1, g_Bt + (size_t)n0n * DIM);
                CP_COMMIT();
                if (tid < TN) s_yy[buf ^ 1][tid] = g_YY[n0n + tid];
                else          s_mu[buf ^ 1][tid - TN] = mu[n0n + tid - TN];
            }
            if (more) asm volatile("cp.async.wait_group 1;" ::: "memory");
            else      asm volatile("cp.async.wait_group 0;" ::: "memory");
            __syncthreads();

            // ---- MMA: 128x128x256 via m16n8k16 ----
            float acc[2][8][4];
            #pragma unroll
            for (int mf = 0; mf < 2; mf++)
                #pragma unroll
                for (int nf = 0; nf < 8; nf++)
                    #pragma unroll
                    for (int e = 0; e < 4; e++) acc[mf][nf][e] = 0.f;

            #pragma unroll 4
            for (int kk = 0; kk < 16; kk++) {
                const uint32_t kcOff = (uint32_t)((kk >> 2) << 14);
                const uint32_t kbA   = (uint32_t)(((kk & 3) << 5) + aKl);
                const uint32_t kbB   = (uint32_t)(((kk & 3) << 5) + bKl);

                uint32_t a[2][4];
                #pragma unroll
                for (int mf = 0; mf < 2; mf++)
                    ldsm_x4(a[mf], uA + kcOff + (uint32_t)((rA0 + 16 * mf) << 7) + (kbA ^ swA));

                uint32_t b[4][4];
                #pragma unroll
                for (int np = 0; np < 4; np++)
                    ldsm_x4(b[np], uB + kcOff + (uint32_t)((rB0 + 16 * np) << 7) + (kbB ^ swB));

                #pragma unroll
                for (int mf = 0; mf < 2; mf++)
                    #pragma unroll
                    for (int nf = 0; nf < 8; nf++)
                        mma_16816(acc[mf][nf], a[mf],
                                  b[nf >> 1][(nf & 1) * 2], b[nf >> 1][(nf & 1) * 2 + 1]);
            }

            // ---- epilogue: screening min over the 64 elements ----
            float yv[16];
            #pragma unroll
            for (int k2 = 0; k2 < 16; k2++)
                yv[k2] = s_yy[buf][warp_n + (k2 >> 1) * 8 + 2 * (lane & 3) + (k2 & 1)];

            float minlb = 3.4e38f;
            #pragma unroll
            for (int mf = 0; mf < 2; mf++)
                #pragma unroll
                for (int nf = 0; nf < 8; nf++)
                    #pragma unroll
                    for (int e = 0; e < 4; e++) {
                        const float q  = xv[mf * 2 + (e >> 1)] + yv[nf * 2 + (e & 1)];
                        const float s  = fmaf(-2.f, acc[mf][nf][e], q);
                        const float lb = fmaf(-0.0078125f, q, s);  // bf16-error margin
                        minlb = fminf(minlb, lb);
                    }

            if (minlb < sCut) {   // rare: exact fp32 recompute for flagged elements
                const int n0 = ((i + tl) & 63) * TN;
                #pragma unroll 1
                for (int mf = 0; mf < 2; mf++)
                    for (int nf = 0; nf < 8; nf++)
                        for (int e = 0; e < 4; e++) {
                            const float q  = xv[mf * 2 + (e >> 1)] + yv[nf * 2 + (e & 1)];
                            const float s  = fmaf(-2.f, acc[mf][nf][e], q);
                            const float lb = fmaf(-0.0078125f, q, s);
                            if (lb < sCut) {
                                const int rg = row0 + warp_m + mf * 16 + (lane >> 2) + 8 * (e >> 1);
                                const int cg = n0 + warp_n + nf * 8 + 2 * (lane & 3) + (e & 1);
                                const float* xr = Xtest  + (size_t)rg * DIM;
                                const float* yr = Xtrain + (size_t)cg * DIM;
                                float cr = 0.f;
                                #pragma unroll 8
                                for (int d = 0; d < DIM; d++) cr = fmaf(xr[d], yr[d], cr);
                                const float se = fmaxf(fmaf(-2.f, cr, g_XX[rg] + g_YY[cg]), 0.f);
                                const float ev = expf(se * negInv);
                                if (ev != 0.f)
                                    atomicAdd(&out[rg], sv * ev * s_mu[buf][warp_n + nf * 8 + 2 * (lane & 3) + (e & 1)]);
                            }
                        }
            }
            __syncthreads();   // epilogue done before buffers are overwritten
        }
        i = seg_end;
    }
}

// ============================================================================
// kernel_launch: inputs in metadata order:
//   0 Xtest, 1 Xtrain, 2 mu, 3 mean_const, 4 lengthscale, 5 signal_var
// ============================================================================
extern "C" void kernel_launch(void* const* d_in, const int* in_sizes, int n_in,
                              void* d_out, int out_size)
{
    const float* Xtest      = (const float*)d_in[0];
    const float* Xtrain     = (const float*)d_in[1];
    const float* mu         = (const float*)d_in[2];
    const float* mean_const = (const float*)d_in[3];
    const float* lengthsc   = (const float*)d_in[4];
    const float* signal_var = (const float*)d_in[5];
    float* out = (float*)d_out;

    const int DYN = 3 * 65536 + 1024;
    cudaFuncSetAttribute(gp_hmma_kernel, cudaFuncAttributeMaxDynamicSharedMemorySize, DYN);

    gp_precompute_kernel<<<(NTEST + NTRAIN) / 8, 256>>>(Xtest, Xtrain, mean_const, out);
    gp_hmma_kernel<<<GRID, 256, DYN>>>(Xtest, Xtrain, mu, lengthsc, signal_var, out);
}

// round 5
// speedup vs baseline: 6.8610x; 1.9690x over previous
#include <cuda_runtime.h>
#include <cuda_bf16.h>
#include <math.h>
#include <stdint.h>

// ============================================================================
// Problem constants (fixed by reference setup_inputs)
// ============================================================================
#define NTEST  8192
#define NTRAIN 8192
#define DIM    256

#define TM 128
#define TN 128
#define N_ROW_TILES (NTEST / TM)               // 64
#define N_COL_TILES (NTRAIN / TN)              // 64
#define TOT_TILES   (N_ROW_TILES * N_COL_TILES) // 4096
#define GRID 296                                // 2 balanced waves on 148 SMs

// Scratch (__device__ globals: allocation-free rule)
__device__ float g_XX[NTEST];
__device__ float g_YY[NTRAIN];
__device__ __align__(128) __nv_bfloat16 g_At[NTEST  * DIM];
__device__ __align__(128) __nv_bfloat16 g_Bt[NTRAIN * DIM];

// ============================================================================
// helpers
// ============================================================================
__device__ __forceinline__ uint32_t smem_u32(const void* p) {
    uint32_t a;
    asm("{ .reg .u64 t; cvta.to.shared.u64 t, %1; cvt.u32.u64 %0, t; }" : "=r"(a) : "l"(p));
    return a;
}
__device__ __forceinline__ void cp16(uint32_t dst, const void* src) {
    asm volatile("cp.async.cg.shared.global [%0], [%1], 16;" :: "r"(dst), "l"(src));
}
#define CP_COMMIT() asm volatile("cp.async.commit_group;" ::: "memory")

__device__ __forceinline__ void ldsm_x4(uint32_t (&r)[4], uint32_t addr) {
    asm volatile("ldmatrix.sync.aligned.m8n8.x4.shared.b16 {%0,%1,%2,%3}, [%4];"
                 : "=r"(r[0]), "=r"(r[1]), "=r"(r[2]), "=r"(r[3]) : "r"(addr));
}
__device__ __forceinline__ void mma_16816(float (&c)[4], const uint32_t (&a)[4],
                                          uint32_t b0, uint32_t b1) {
    asm volatile(
        "mma.sync.aligned.m16n8k16.row.col.f32.bf16.bf16.f32 "
        "{%0,%1,%2,%3}, {%4,%5,%6,%7}, {%8,%9}, {%0,%1,%2,%3};"
        : "+f"(c[0]), "+f"(c[1]), "+f"(c[2]), "+f"(c[3])
        : "r"(a[0]), "r"(a[1]), "r"(a[2]), "r"(a[3]), "r"(b0), "r"(b1));
}

// ============================================================================
// Kernel 1: norms + bf16 conversion + out[] = mean_const init
// ============================================================================
__global__ void gp_precompute_kernel(const float* __restrict__ Xtest,
                                     const float* __restrict__ Xtrain,
                                     const float* __restrict__ mean_const,
                                     float* __restrict__ out)
{
    const int warp = threadIdx.x >> 5;
    const int lane = threadIdx.x & 31;
    int row = blockIdx.x * 8 + warp;
    if (row >= NTEST + NTRAIN) return;

    const float* X; float* dst; __nv_bfloat16* bdst; bool isTest;
    if (row < NTEST) { X = Xtest;  dst = g_XX; bdst = g_At; isTest = true; }
    else { row -= NTEST; X = Xtrain; dst = g_YY; bdst = g_Bt; isTest = false; }

    const float* p = X + (size_t)row * DIM;
    __nv_bfloat16* bp = bdst + (size_t)row * DIM;
    float s = 0.f;
    #pragma unroll
    for (int d = 0; d < DIM / 32; d++) {
        float v = p[lane + d * 32];
        s = fmaf(v, v, s);
        bp[lane + d * 32] = __float2bfloat16_rn(v);
    }
    #pragma unroll
    for (int o = 16; o > 0; o >>= 1) s += __shfl_xor_sync(0xffffffffu, s, o);
    if (lane == 0) {
        dst[row] = s;
        if (isTest) out[row] = *mean_const;
    }
}

// ============================================================================
// Kernel 2: HMMA screening GEMM + underflow-exact epilogue.
// k-loop uses explicit fragment double-buffering (prefetch kk+1 while HMMA kk).
// Epilogue uses a warp-level rigorous screen: lb >= (127/128)*qmin - 2*cmax.
// ============================================================================
__global__ __launch_bounds__(256, 1)
void gp_hmma_kernel(const float* __restrict__ Xtest,
                    const float* __restrict__ Xtrain,
                    const float* __restrict__ mu,
                    const float* __restrict__ ls_p,
                    const float* __restrict__ sv_p,
                    float* __restrict__ out)
{
    extern __shared__ char dsm[];
    __shared__ float s_yy[2][TN];
    __shared__ float s_mu[2][TN];

    const int tid  = threadIdx.x;
    const int wid  = tid >> 5;
    const int lane = tid & 31;
    const int bid  = blockIdx.x;

    const uint32_t dsm_u = smem_u32(dsm);
    const uint32_t uA  = (dsm_u + 1023u) & ~1023u;
    const uint32_t uB0 = uA  + 65536u;
    const uint32_t uB1 = uB0 + 65536u;

    const int warp_m = (wid & 3) * 32;   // 4 warps along M
    const int warp_n = (wid >> 2) * 64;  // 2 warps along N

    // ldmatrix lane geometry
    const int rA0   = warp_m + (lane & 15);
    const uint32_t swA = (uint32_t)((rA0 & 7) << 4);
    const uint32_t aKl = (uint32_t)((lane >> 4) << 4);
    const int rB0   = warp_n + (lane & 7) + ((lane >> 4) << 3);
    const uint32_t swB = (uint32_t)((rB0 & 7) << 4);
    const uint32_t bKl = (uint32_t)(((lane >> 3) & 1) << 4);

    // precomputed per-warp ldmatrix row bases
    uint32_t rbaseA[2], rbaseB[4];
    #pragma unroll
    for (int mf = 0; mf < 2; mf++) rbaseA[mf] = uA + (uint32_t)((rA0 + 16 * mf) << 7);
    #pragma unroll
    for (int np = 0; np < 4; np++) rbaseB[np] = (uint32_t)((rB0 + 16 * np) << 7);

    const float l      = *ls_p;
    const float negInv = -0.5f / (l * l);
    const float sCut   = 211.0f * l * l;   // expf == exactly 0 above this
    const float sv     = *sv_p;

    const int t_begin = (int)(((long long)bid     * TOT_TILES) / GRID);
    const int t_end   = (int)(((long long)(bid+1) * TOT_TILES) / GRID);

    auto fill_tile = [&](uint32_t ubase, const __nv_bfloat16* src) {
        #pragma unroll
        for (int q0 = 0; q0 < 16; q0++) {
            const int q = q0 * 256 + tid;
            const int r = q >> 5, c16 = q & 31;
            const uint32_t dst = ubase + (uint32_t)(((c16 >> 3) << 14) + (r << 7)
                                + (((c16 & 7) << 4) ^ ((r & 7) << 4)));
            cp16(dst, src + r * DIM + c16 * 8);
        }
    };

    int i = t_begin;
    while (i < t_end) {
        const int rt      = i >> 6;
        const int seg_end = min(t_end, (rt + 1) << 6);
        const int n       = seg_end - i;
        const int row0    = rt * TM;

        fill_tile(uA, g_At + (size_t)row0 * DIM);
        CP_COMMIT();
        {
            const int n0 = (i & 63) * TN;
            fill_tile(uB0, g_Bt + (size_t)n0 * DIM);
            CP_COMMIT();
            if (tid < TN) s_yy[0][tid] = g_YY[n0 + tid];
            else          s_mu[0][tid - TN] = mu[n0 + tid - TN];
        }

        // per-thread xx values (4 rows) + warp row-min
        float xv[4];
        #pragma unroll
        for (int j = 0; j < 4; j++) xv[j] = g_XX[row0 + warp_m + (lane >> 2) + 8 * j];
        float xmin = fminf(fminf(xv[0], xv[1]), fminf(xv[2], xv[3]));
        #pragma unroll
        for (int o = 16; o > 0; o >>= 1) xmin = fminf(xmin, __shfl_xor_sync(0xffffffffu, xmin, o));

        for (int tl = 0; tl < n; tl++) {
            const int buf = tl & 1;
            const uint32_t uB = buf ? uB1 : uB0;

            const bool more = (tl + 1 < n);
            if (more) {
                const int n0n = ((i + tl + 1) & 63) * TN;
                fill_tile(buf ? uB0 : uB1, g_Bt + (size_t)n0n * DIM);
                CP_COMMIT();
                if (tid < TN) s_yy[buf ^ 1][tid] = g_YY[n0n + tid];
                else          s_mu[buf ^ 1][tid - TN] = mu[n0n + tid - TN];
            }
            if (more) asm volatile("cp.async.wait_group 1;" ::: "memory");
            else      asm volatile("cp.async.wait_group 0;" ::: "memory");
            __syncthreads();

            // ---- MMA: 128x128x256, fragment-double-buffered k loop ----
            float acc[2][8][4];
            #pragma unroll
            for (int mf = 0; mf < 2; mf++)
                #pragma unroll
                for (int nf = 0; nf < 8; nf++)
                    #pragma unroll
                    for (int e = 0; e < 4; e++) acc[mf][nf][e] = 0.f;

            uint32_t a[2][2][4], b[2][4][4];

            auto ld_frags = [&](int kk, uint32_t (&af)[2][4], uint32_t (&bf)[4][4]) {
                const uint32_t kcOff = (uint32_t)((kk >> 2) << 14);
                const uint32_t oA = kcOff + ((((uint32_t)(kk & 3) << 5) + aKl) ^ swA);
                const uint32_t oB = kcOff + ((((uint32_t)(kk & 3) << 5) + bKl) ^ swB);
                #pragma unroll
                for (int mf = 0; mf < 2; mf++) ldsm_x4(af[mf], rbaseA[mf] + oA);
                #pragma unroll
                for (int np = 0; np < 4; np++) ldsm_x4(bf[np], uB + rbaseB[np] + oB);
            };

            ld_frags(0, a[0], b[0]);
            #pragma unroll
            for (int kk = 0; kk < 16; kk++) {
                const int cur = kk & 1;
                if (kk < 15) ld_frags(kk + 1, a[cur ^ 1], b[cur ^ 1]);
                #pragma unroll
                for (int mf = 0; mf < 2; mf++)
                    #pragma unroll
                    for (int nf = 0; nf < 8; nf++)
                        mma_16816(acc[mf][nf], a[cur][mf],
                                  b[cur][nf >> 1][(nf & 1) * 2], b[cur][nf >> 1][(nf & 1) * 2 + 1]);
            }

            // ---- epilogue: warp-level rigorous screen ----
            float cmax = -3.4e38f;
            #pragma unroll
            for (int mf = 0; mf < 2; mf++)
                #pragma unroll
                for (int nf = 0; nf < 8; nf++)
                    #pragma unroll
                    for (int e = 0; e < 4; e++) cmax = fmaxf(cmax, acc[mf][nf][e]);
            #pragma unroll
            for (int o = 16; o > 0; o >>= 1) cmax = fmaxf(cmax, __shfl_xor_sync(0xffffffffu, cmax, o));

            float ymin = fminf(s_yy[buf][warp_n + lane], s_yy[buf][warp_n + 32 + lane]);
            #pragma unroll
            for (int o = 16; o > 0; o >>= 1) ymin = fminf(ymin, __shfl_xor_sync(0xffffffffu, ymin, o));

            const float qmin  = xmin + ymin;                       // q = xx+yy >= 0
            const float lbmin = fmaf(-0.0078125f, qmin, fmaf(-2.f, cmax, qmin));

            if (lbmin < sCut) {   // rare: per-element check + exact fp32 recompute
                float yv[16];
                #pragma unroll
                for (int k2 = 0; k2 < 16; k2++)
                    yv[k2] = s_yy[buf][warp_n + (k2 >> 1) * 8 + 2 * (lane & 3) + (k2 & 1)];
                const int n0 = ((i + tl) & 63) * TN;
                #pragma unroll 1
                for (int mf = 0; mf < 2; mf++)
                    for (int nf = 0; nf < 8; nf++)
                        for (int e = 0; e < 4; e++) {
                            const float q  = xv[mf * 2 + (e >> 1)] + yv[nf * 2 + (e & 1)];
                            const float s  = fmaf(-2.f, acc[mf][nf][e], q);
                            const float lb = fmaf(-0.0078125f, q, s);
                            if (lb < sCut) {
                                const int rg = row0 + warp_m + mf * 16 + (lane >> 2) + 8 * (e >> 1);
                                const int cg = n0 + warp_n + nf * 8 + 2 * (lane & 3) + (e & 1);
                                const float* xr = Xtest  + (size_t)rg * DIM;
                                const float* yr = Xtrain + (size_t)cg * DIM;
                                float cr = 0.f;
                                #pragma unroll 8
                                for (int d = 0; d < DIM; d++) cr = fmaf(xr[d], yr[d], cr);
                                const float se = fmaxf(fmaf(-2.f, cr, g_XX[rg] + g_YY[cg]), 0.f);
                                const float ev = expf(se * negInv);
                                if (ev != 0.f)
                                    atomicAdd(&out[rg], sv * ev * s_mu[buf][warp_n + nf * 8 + 2 * (lane & 3) + (e & 1)]);
                            }
                        }
            }
            __syncthreads();   // epilogue done before buffers are overwritten
        }
        i = seg_end;
    }
}

// ============================================================================
// kernel_launch: inputs in metadata order:
//   0 Xtest, 1 Xtrain, 2 mu, 3 mean_const, 4 lengthscale, 5 signal_var
// ============================================================================
extern "C" void kernel_launch(void* const* d_in, const int* in_sizes, int n_in,
                              void* d_out, int out_size)
{
    const float* Xtest      = (const float*)d_in[0];
    const float* Xtrain     = (const float*)d_in[1];
    const float* mu         = (const float*)d_in[2];
    const float* mean_const = (const float*)d_in[3];
    const float* lengthsc   = (const float*)d_in[4];
    const float* signal_var = (const float*)d_in[5];
    float* out = (float*)d_out;

    const int DYN = 3 * 65536 + 1024;
    cudaFuncSetAttribute(gp_hmma_kernel, cudaFuncAttributeMaxDynamicSharedMemorySize, DYN);

    gp_precompute_kernel<<<(NTEST + NTRAIN) / 8, 256>>>(Xtest, Xtrain, mean_const, out);
    gp_hmma_kernel<<<GRID, 256, DYN>>>(Xtest, Xtrain, mu, lengthsc, signal_var, out);
}